// round 7
// baseline (speedup 1.0000x reference)
#include <cuda_runtime.h>
#include <mma.h>
#include <cstdint>
#include <cstdio>

using namespace nvcuda;

// Problem constants
#define BB   16
#define NSEQ 512
#define DM   768
#define HH   12
#define DK   64
#define NDE  32

#define MTOT (BB * NSEQ)   // 8192 rows

// ---------------- scratch (device globals; allocation-free) ----------------
__device__ float g_xln[MTOT * DM];
__device__ float g_q[MTOT * DM];
__device__ float g_k[MTOT * DM];
__device__ float g_v[MTOT * DM];
__device__ float g_oh[MTOT * DM];
__device__ int   g_px[MTOT];
__device__ int   g_py[MTOT];

// ---------------- LayerNorm ----------------
__global__ __launch_bounds__(256) void ln_kernel(const float* __restrict__ x,
                                                 const float* __restrict__ gamma,
                                                 const float* __restrict__ beta,
                                                 float* __restrict__ y) {
    int row = blockIdx.x;
    int tid = threadIdx.x;
    const float* xr = x + (size_t)row * DM;
    float v0 = xr[tid], v1 = xr[tid + 256], v2 = xr[tid + 512];
    __shared__ float red[256];
    red[tid] = v0 + v1 + v2;
    __syncthreads();
    for (int o = 128; o; o >>= 1) { if (tid < o) red[tid] += red[tid + o]; __syncthreads(); }
    float mean = red[0] * (1.0f / 768.0f);
    __syncthreads();
    float d0 = v0 - mean, d1 = v1 - mean, d2 = v2 - mean;
    red[tid] = d0 * d0 + d1 * d1 + d2 * d2;
    __syncthreads();
    for (int o = 128; o; o >>= 1) { if (tid < o) red[tid] += red[tid + o]; __syncthreads(); }
    float rs = rsqrtf(red[0] * (1.0f / 768.0f) + 1e-5f);
    float* yr = y + (size_t)row * DM;
    yr[tid]       = d0 * rs * gamma[tid]       + beta[tid];
    yr[tid + 256] = d1 * rs * gamma[tid + 256] + beta[tid + 256];
    yr[tid + 512] = d2 * rs * gamma[tid + 512] + beta[tid + 512];
}

// ---------------- Patch bins (replicates argmax-over-mask incl. all-False -> 0) ----------------
__global__ void bins_kernel(const float* __restrict__ boxes,
                            const int* __restrict__ img,
                            int* __restrict__ px, int* __restrict__ py) {
    int t = blockIdx.x * blockDim.x + threadIdx.x;
    if (t >= MTOT) return;
    int b = t / NSEQ;
    float wf = (float)img[b * 4 + 0];
    float hf = (float)img[b * 4 + 1];
    const float* bx = boxes + (size_t)t * 4;
    float spa_w = floorf(wf / 11.0f);
    float spa_h = floorf(hf / 11.0f);
    float cx = floorf((bx[0] * wf + bx[2] * wf) * 0.5f);
    float cy = floorf((bx[1] * hf + bx[3] * hf) * 0.5f);
    int pxi = 0, pyi = 0;
    for (int i = 0; i < 11; i++) {
        float lo = (float)i * spa_w, hi = (float)(i + 1) * spa_w;
        if (lo <= cx && cx <= hi) { pxi = i; break; }
    }
    for (int i = 0; i < 11; i++) {
        float lo = (float)i * spa_h, hi = (float)(i + 1) * spa_h;
        if (lo <= cy && cy <= hi) { pyi = i; break; }
    }
    px[t] = pxi;
    py[t] = pyi;
}

// ---------------- Generic TF32 GEMM: C[m,n] = sum_k A[m,K]*W[n,K] + bias[n] ----------------
// Block 128x64, 8 warps (4x2 of 32x32), K-step 16.
__global__ __launch_bounds__(256) void gemm_tf32(const float* __restrict__ A,
                                                 const float* __restrict__ W,
                                                 const float* __restrict__ bias,
                                                 float* __restrict__ C,
                                                 int M, int Nn, int K) {
    __shared__ float As[128][24];
    __shared__ float Bs[16][72];
    __shared__ float stg[8][16 * 20];
    int tid = threadIdx.x;
    int w = tid >> 5, lane = tid & 31;
    int wm = w & 3, wn = w >> 2;          // 4 row-warps x 2 col-warps
    int m0 = blockIdx.y * 128;
    int n0 = blockIdx.x * 64;

    wmma::fragment<wmma::accumulator, 16, 16, 8, float> acc[2][2];
    for (int i = 0; i < 2; i++)
        for (int j = 0; j < 2; j++) wmma::fill_fragment(acc[i][j], 0.0f);

    for (int k0 = 0; k0 < K; k0 += 16) {
        for (int i = tid; i < 128 * 16; i += 256) {
            int m = i >> 4, kk = i & 15;
            As[m][kk] = A[(size_t)(m0 + m) * K + k0 + kk];
        }
        for (int i = tid; i < 64 * 16; i += 256) {
            int kk = i & 15, n = i >> 4;
            Bs[kk][n] = W[(size_t)(n0 + n) * K + k0 + kk];
        }
        __syncthreads();
        for (int kk = 0; kk < 16; kk += 8) {
            wmma::fragment<wmma::matrix_a, 16, 16, 8, wmma::precision::tf32, wmma::row_major> af[2];
            wmma::fragment<wmma::matrix_b, 16, 16, 8, wmma::precision::tf32, wmma::row_major> bf[2];
            for (int i = 0; i < 2; i++) {
                wmma::load_matrix_sync(af[i], &As[wm * 32 + i * 16][kk], 24);
                for (int e = 0; e < af[i].num_elements; e++) af[i].x[e] = wmma::__float_to_tf32(af[i].x[e]);
                wmma::load_matrix_sync(bf[i], &Bs[kk][wn * 32 + i * 16], 72);
                for (int e = 0; e < bf[i].num_elements; e++) bf[i].x[e] = wmma::__float_to_tf32(bf[i].x[e]);
            }
            for (int i = 0; i < 2; i++)
                for (int j = 0; j < 2; j++) wmma::mma_sync(acc[i][j], af[i], bf[j], acc[i][j]);
        }
        __syncthreads();
    }
    // epilogue: per-warp staging, add bias, coalesced store
    for (int i = 0; i < 2; i++)
        for (int j = 0; j < 2; j++) {
            wmma::store_matrix_sync(stg[w], acc[i][j], 20, wmma::mem_row_major);
            __syncwarp();
            int r0 = m0 + wm * 32 + i * 16;
            int c0 = n0 + wn * 32 + j * 16;
            for (int e = lane; e < 256; e += 32) {
                int r = e >> 4, c = e & 15;
                C[(size_t)(r0 + r) * Nn + c0 + c] = stg[w][r * 20 + c] + bias[c0 + c];
            }
            __syncwarp();
        }
}

// ---------------- Fused attention: S=QK^T/8 + bias -> softmax -> att out + P*V ----------------
// Block: 32 query rows x all 512 keys, one (b,h). 8 warps / 256 threads.
#define PS_LD 520   // padded leading dim for the 32x512 S/P tile

__global__ __launch_bounds__(256) void attn_kernel(const float* __restrict__ q,
                                                   const float* __restrict__ k,
                                                   const float* __restrict__ v,
                                                   const int* __restrict__ px,
                                                   const int* __restrict__ py,
                                                   const float* __restrict__ demb,
                                                   float* __restrict__ att,
                                                   float* __restrict__ oh) {
    extern __shared__ float sm[];
    float* Ps  = sm;                            // 32 x PS_LD
    int*  pxk  = (int*)(sm + 32 * PS_LD);       // 512
    int*  pyk  = pxk + 512;                     // 512
    int*  pxq  = pyk + 512;                     // 32
    int*  pyq  = pxq + 32;                      // 32
    float* db  = (float*)(pyq + 32);            // 32 (dist_emb column h)

    int q0 = blockIdx.x * 32;
    int h  = blockIdx.y;
    int b  = blockIdx.z;
    int tid = threadIdx.x;
    int w = tid >> 5, lane = tid & 31;

    for (int c = tid; c < 512; c += 256) { pxk[c] = px[b * NSEQ + c]; pyk[c] = py[b * NSEQ + c]; }
    if (tid < 32) {
        pxq[tid] = px[b * NSEQ + q0 + tid];
        pyq[tid] = py[b * NSEQ + q0 + tid];
        db[tid]  = demb[tid * HH + h];
    }

    // ---- S = Q K^T  (each warp: 32x64 slice of the 32x512 tile) ----
    wmma::fragment<wmma::accumulator, 16, 16, 8, float> acc[2][4];
    for (int mi = 0; mi < 2; mi++)
        for (int ni = 0; ni < 4; ni++) wmma::fill_fragment(acc[mi][ni], 0.0f);

    const float* qbase = q + ((size_t)(b * NSEQ + q0)) * DM + h * DK;
    const float* kbase = k + ((size_t)(b * NSEQ + w * 64)) * DM + h * DK;
    for (int kk = 0; kk < DK; kk += 8) {
        wmma::fragment<wmma::matrix_a, 16, 16, 8, wmma::precision::tf32, wmma::row_major> a[2];
        for (int mi = 0; mi < 2; mi++) {
            wmma::load_matrix_sync(a[mi], qbase + (size_t)mi * 16 * DM + kk, DM);
            for (int e = 0; e < a[mi].num_elements; e++) a[mi].x[e] = wmma::__float_to_tf32(a[mi].x[e]);
        }
        for (int ni = 0; ni < 4; ni++) {
            wmma::fragment<wmma::matrix_b, 16, 16, 8, wmma::precision::tf32, wmma::col_major> bfr;
            wmma::load_matrix_sync(bfr, kbase + (size_t)ni * 16 * DM + kk, DM);
            for (int e = 0; e < bfr.num_elements; e++) bfr.x[e] = wmma::__float_to_tf32(bfr.x[e]);
            for (int mi = 0; mi < 2; mi++) wmma::mma_sync(acc[mi][ni], a[mi], bfr, acc[mi][ni]);
        }
    }
    for (int mi = 0; mi < 2; mi++)
        for (int ni = 0; ni < 4; ni++) {
            for (int e = 0; e < acc[mi][ni].num_elements; e++) acc[mi][ni].x[e] *= 0.125f;  // 1/sqrt(64)
            wmma::store_matrix_sync(&Ps[(mi * 16) * PS_LD + w * 64 + ni * 16], acc[mi][ni],
                                    PS_LD, wmma::mem_row_major);
        }
    __syncthreads();

    // ---- bias + softmax (warp w handles rows 4w..4w+3), write att ----
    float* attb = att + ((size_t)(b * HH + h) * NSEQ + q0) * NSEQ;
    for (int rr = 0; rr < 4; rr++) {
        int r = w * 4 + rr;
        int pxr = pxq[r], pyr = pyq[r];
        float mx = -1e30f;
        for (int c = lane; c < 512; c += 32) {
            int dx = pxk[c] - pxr, dy = pyk[c] - pyr;
            int bin = (int)(sqrtf((float)(dx * dx + dy * dy)) * 2.0f);
            float val = Ps[r * PS_LD + c] + db[bin];
            Ps[r * PS_LD + c] = val;
            mx = fmaxf(mx, val);
        }
        for (int o = 16; o; o >>= 1) mx = fmaxf(mx, __shfl_xor_sync(0xffffffffu, mx, o));
        float sum = 0.f;
        for (int c = lane; c < 512; c += 32) {
            float e = expf(Ps[r * PS_LD + c] - mx);
            Ps[r * PS_LD + c] = e;
            sum += e;
        }
        for (int o = 16; o; o >>= 1) sum += __shfl_xor_sync(0xffffffffu, sum, o);
        float inv = 1.0f / sum;
        for (int c = lane; c < 512; c += 32) {
            float p = Ps[r * PS_LD + c] * inv;
            Ps[r * PS_LD + c] = p;
            attb[(size_t)r * NSEQ + c] = p;
        }
    }
    __syncthreads();

    // ---- out = P V (32x64; warp w -> 16x16 tile (mi = w>>2, ni = w&3)) ----
    int mi = w >> 2, ni = w & 3;
    wmma::fragment<wmma::accumulator, 16, 16, 8, float> acc2;
    wmma::fill_fragment(acc2, 0.0f);
    const float* vbase = v + ((size_t)(b * NSEQ)) * DM + h * DK + ni * 16;
    for (int ks = 0; ks < 512; ks += 8) {
        wmma::fragment<wmma::matrix_a, 16, 16, 8, wmma::precision::tf32, wmma::row_major> a2;
        wmma::load_matrix_sync(a2, &Ps[(mi * 16) * PS_LD + ks], PS_LD);
        for (int e = 0; e < a2.num_elements; e++) a2.x[e] = wmma::__float_to_tf32(a2.x[e]);
        wmma::fragment<wmma::matrix_b, 16, 16, 8, wmma::precision::tf32, wmma::row_major> b2;
        wmma::load_matrix_sync(b2, vbase + (size_t)ks * DM, DM);
        for (int e = 0; e < b2.num_elements; e++) b2.x[e] = wmma::__float_to_tf32(b2.x[e]);
        wmma::mma_sync(acc2, a2, b2, acc2);
    }
    wmma::store_matrix_sync(oh + ((size_t)(b * NSEQ + q0 + mi * 16)) * DM + h * DK + ni * 16,
                            acc2, DM, wmma::mem_row_major);
}

// ---------------- launch ----------------
extern "C" void kernel_launch(void* const* d_in, const int* in_sizes, int n_in,
                              void* d_out, int out_size) {
    const float* features = (const float*)d_in[0];
    const float* boxes    = (const float*)d_in[1];
    const int*   img      = (const int*)d_in[2];
    const float* Wq = (const float*)d_in[3];  const float* bq = (const float*)d_in[4];
    const float* Wk = (const float*)d_in[5];  const float* bk = (const float*)d_in[6];
    const float* Wv = (const float*)d_in[7];  const float* bv = (const float*)d_in[8];
    const float* Wo = (const float*)d_in[9];  const float* bo = (const float*)d_in[10];
    const float* gamma = (const float*)d_in[11];
    const float* beta  = (const float*)d_in[12];
    const float* demb  = (const float*)d_in[13];

    float* out = (float*)d_out;                       // (B, N, D)
    float* att = out + (size_t)BB * NSEQ * DM;        // (B, H, N, N)

    float *xln, *qb, *kb, *vb, *ohb;
    int *pxp, *pyp;
    cudaGetSymbolAddress((void**)&xln, g_xln);
    cudaGetSymbolAddress((void**)&qb,  g_q);
    cudaGetSymbolAddress((void**)&kb,  g_k);
    cudaGetSymbolAddress((void**)&vb,  g_v);
    cudaGetSymbolAddress((void**)&ohb, g_oh);
    cudaGetSymbolAddress((void**)&pxp, g_px);
    cudaGetSymbolAddress((void**)&pyp, g_py);

    ln_kernel<<<MTOT, 256>>>(features, gamma, beta, xln);
    bins_kernel<<<(MTOT + 255) / 256, 256>>>(boxes, img, pxp, pyp);

    dim3 gg(DM / 64, MTOT / 128);
    gemm_tf32<<<gg, 256>>>(xln, Wq, bq, qb, MTOT, DM, DM);
    gemm_tf32<<<gg, 256>>>(xln, Wk, bk, kb, MTOT, DM, DM);
    gemm_tf32<<<gg, 256>>>(xln, Wv, bv, vb, MTOT, DM, DM);

    int smem = 32 * PS_LD * 4 + (512 * 2 + 32 * 2) * 4 + 32 * 4;
    cudaFuncSetAttribute(attn_kernel, cudaFuncAttributeMaxDynamicSharedMemorySize, smem);
    attn_kernel<<<dim3(NSEQ / 32, HH, BB), 256, smem>>>(qb, kb, vb, pxp, pyp, demb, att, ohb);

    gemm_tf32<<<gg, 256>>>(ohb, Wo, bo, out, MTOT, DM, DM);
}

// round 9
// speedup vs baseline: 1.4554x; 1.4554x over previous
#include <cuda_runtime.h>
#include <mma.h>
#include <cstdint>
#include <cstdio>

using namespace nvcuda;

// Problem constants
#define BB   16
#define NSEQ 512
#define DM   768
#define HH   12
#define DK   64
#define NDE  32

#define MTOT (BB * NSEQ)   // 8192 rows

// ---------------- scratch (device globals; allocation-free) ----------------
__device__ float g_xln[MTOT * DM];
__device__ float g_q[MTOT * DM];
__device__ float g_k[MTOT * DM];
__device__ float g_v[MTOT * DM];
__device__ float g_oh[MTOT * DM];
__device__ int   g_px[MTOT];
__device__ int   g_py[MTOT];

// ---------------- LayerNorm ----------------
__global__ __launch_bounds__(256) void ln_kernel(const float* __restrict__ x,
                                                 const float* __restrict__ gamma,
                                                 const float* __restrict__ beta,
                                                 float* __restrict__ y) {
    int row = blockIdx.x;
    int tid = threadIdx.x;
    const float* xr = x + (size_t)row * DM;
    float v0 = xr[tid], v1 = xr[tid + 256], v2 = xr[tid + 512];
    __shared__ float red[256];
    red[tid] = v0 + v1 + v2;
    __syncthreads();
    for (int o = 128; o; o >>= 1) { if (tid < o) red[tid] += red[tid + o]; __syncthreads(); }
    float mean = red[0] * (1.0f / 768.0f);
    __syncthreads();
    float d0 = v0 - mean, d1 = v1 - mean, d2 = v2 - mean;
    red[tid] = d0 * d0 + d1 * d1 + d2 * d2;
    __syncthreads();
    for (int o = 128; o; o >>= 1) { if (tid < o) red[tid] += red[tid + o]; __syncthreads(); }
    float rs = rsqrtf(red[0] * (1.0f / 768.0f) + 1e-5f);
    float* yr = y + (size_t)row * DM;
    yr[tid]       = d0 * rs * gamma[tid]       + beta[tid];
    yr[tid + 256] = d1 * rs * gamma[tid + 256] + beta[tid + 256];
    yr[tid + 512] = d2 * rs * gamma[tid + 512] + beta[tid + 512];
}

// ---------------- Patch bins ----------------
__global__ void bins_kernel(const float* __restrict__ boxes,
                            const int* __restrict__ img,
                            int* __restrict__ px, int* __restrict__ py) {
    int t = blockIdx.x * blockDim.x + threadIdx.x;
    if (t >= MTOT) return;
    int b = t / NSEQ;
    float wf = (float)img[b * 4 + 0];
    float hf = (float)img[b * 4 + 1];
    const float* bx = boxes + (size_t)t * 4;
    float spa_w = floorf(wf / 11.0f);
    float spa_h = floorf(hf / 11.0f);
    float cx = floorf((bx[0] * wf + bx[2] * wf) * 0.5f);
    float cy = floorf((bx[1] * hf + bx[3] * hf) * 0.5f);
    int pxi = 0, pyi = 0;
    for (int i = 0; i < 11; i++) {
        float lo = (float)i * spa_w, hi = (float)(i + 1) * spa_w;
        if (lo <= cx && cx <= hi) { pxi = i; break; }
    }
    for (int i = 0; i < 11; i++) {
        float lo = (float)i * spa_h, hi = (float)(i + 1) * spa_h;
        if (lo <= cy && cy <= hi) { pyi = i; break; }
    }
    px[t] = pxi;
    py[t] = pyi;
}

// ---------------- Pipelined TF32 GEMM: C = A @ W^T + bias ----------------
// CTA tile 128x128, BK=32, cp.async double buffer. 8 warps, each 64x32.
// W kept K-major in SMEM, consumed as col_major matrix_b (no transpose needed).
#define GBM 128
#define GBN 128
#define GBK 32
#define GLD 36   // padded leading dim (keeps rows 16B-aligned: 36*4=144)

__device__ __forceinline__ void cp_async16(void* smem, const void* gmem) {
    uint32_t s = (uint32_t)__cvta_generic_to_shared(smem);
    asm volatile("cp.async.cg.shared.global [%0], [%1], 16;\n" :: "r"(s), "l"(gmem));
}

__global__ __launch_bounds__(256, 2) void gemm_tf32_pipe(
    const float* __restrict__ A,
    const float* __restrict__ W0, const float* __restrict__ W1, const float* __restrict__ W2,
    const float* __restrict__ b0, const float* __restrict__ b1, const float* __restrict__ b2,
    float* __restrict__ C0, float* __restrict__ C1, float* __restrict__ C2,
    int M, int Nn, int K)
{
    extern __shared__ float sm[];
    float* As = sm;                      // [2][GBM][GLD]
    float* Bs = sm + 2 * GBM * GLD;      // [2][GBN][GLD]  (n-major, k contiguous)

    const float* W    = blockIdx.z == 0 ? W0 : blockIdx.z == 1 ? W1 : W2;
    const float* bias = blockIdx.z == 0 ? b0 : blockIdx.z == 1 ? b1 : b2;
    float*       C    = blockIdx.z == 0 ? C0 : blockIdx.z == 1 ? C1 : C2;

    int tid = threadIdx.x;
    int w = tid >> 5, lane = tid & 31;
    int wm = w >> 2, wn = w & 3;          // 2 row-warps (64 rows) x 4 col-warps (32 cols)
    int m0 = blockIdx.y * GBM;
    int n0 = blockIdx.x * GBN;

    wmma::fragment<wmma::accumulator, 16, 16, 8, float> acc[4][2];
    #pragma unroll
    for (int i = 0; i < 4; i++)
        #pragma unroll
        for (int j = 0; j < 2; j++) wmma::fill_fragment(acc[i][j], 0.0f);

    // 128 rows x 32 k = 1024 float4 per tile; thread handles 4 of them.
    int r_ld  = tid >> 3;          // base row (0..31), +32 per j
    int c4_ld = (tid & 7) * 4;     // k offset within tile

    const int NIT = K / GBK;       // 24

    // prologue: tile 0 -> buf 0
    {
        float* Ab = As; float* Bb = Bs;
        #pragma unroll
        for (int j = 0; j < 4; j++) {
            int r = r_ld + j * 32;
            cp_async16(Ab + r * GLD + c4_ld, A + (size_t)(m0 + r) * K + c4_ld);
            cp_async16(Bb + r * GLD + c4_ld, W + (size_t)(n0 + r) * K + c4_ld);
        }
        asm volatile("cp.async.commit_group;\n" ::: "memory");
    }

    for (int it = 0; it < NIT; it++) {
        asm volatile("cp.async.wait_group 0;\n" ::: "memory");
        __syncthreads();
        if (it + 1 < NIT) {
            int k0 = (it + 1) * GBK;
            float* Ab = As + ((it + 1) & 1) * GBM * GLD;
            float* Bb = Bs + ((it + 1) & 1) * GBN * GLD;
            #pragma unroll
            for (int j = 0; j < 4; j++) {
                int r = r_ld + j * 32;
                cp_async16(Ab + r * GLD + c4_ld, A + (size_t)(m0 + r) * K + k0 + c4_ld);
                cp_async16(Bb + r * GLD + c4_ld, W + (size_t)(n0 + r) * K + k0 + c4_ld);
            }
            asm volatile("cp.async.commit_group;\n" ::: "memory");
        }
        float* Ab = As + (it & 1) * GBM * GLD;
        float* Bb = Bs + (it & 1) * GBN * GLD;
        #pragma unroll
        for (int ks = 0; ks < 4; ks++) {
            wmma::fragment<wmma::matrix_a, 16, 16, 8, wmma::precision::tf32, wmma::row_major> af[4];
            wmma::fragment<wmma::matrix_b, 16, 16, 8, wmma::precision::tf32, wmma::col_major> bf[2];
            #pragma unroll
            for (int mi = 0; mi < 4; mi++) {
                wmma::load_matrix_sync(af[mi], Ab + (wm * 64 + mi * 16) * GLD + ks * 8, GLD);
                #pragma unroll
                for (int e = 0; e < af[mi].num_elements; e++)
                    af[mi].x[e] = wmma::__float_to_tf32(af[mi].x[e]);
            }
            #pragma unroll
            for (int ni = 0; ni < 2; ni++) {
                wmma::load_matrix_sync(bf[ni], Bb + (wn * 32 + ni * 16) * GLD + ks * 8, GLD);
                #pragma unroll
                for (int e = 0; e < bf[ni].num_elements; e++)
                    bf[ni].x[e] = wmma::__float_to_tf32(bf[ni].x[e]);
            }
            #pragma unroll
            for (int mi = 0; mi < 4; mi++)
                #pragma unroll
                for (int ni = 0; ni < 2; ni++)
                    wmma::mma_sync(acc[mi][ni], af[mi], bf[ni], acc[mi][ni]);
        }
        __syncthreads();
    }

    // epilogue: stage per-warp 16x16 tiles through SMEM, add bias, coalesced store
    float* stg = sm + w * (16 * 20);
    #pragma unroll
    for (int mi = 0; mi < 4; mi++)
        #pragma unroll
        for (int ni = 0; ni < 2; ni++) {
            wmma::store_matrix_sync(stg, acc[mi][ni], 20, wmma::mem_row_major);
            __syncwarp();
            int r0 = m0 + wm * 64 + mi * 16;
            int c0 = n0 + wn * 32 + ni * 16;
            #pragma unroll
            for (int e = lane; e < 256; e += 32) {
                int r = e >> 4, c = e & 15;
                C[(size_t)(r0 + r) * Nn + c0 + c] = stg[r * 20 + c] + bias[c0 + c];
            }
            __syncwarp();
        }
}

// ---------------- Fused attention: S=QK^T/8 + bias -> softmax -> att out + P*V ----------------
#define PS_LD 520

__global__ __launch_bounds__(256) void attn_kernel(const float* __restrict__ q,
                                                   const float* __restrict__ k,
                                                   const float* __restrict__ v,
                                                   const int* __restrict__ px,
                                                   const int* __restrict__ py,
                                                   const float* __restrict__ demb,
                                                   float* __restrict__ att,
                                                   float* __restrict__ oh) {
    extern __shared__ float sm[];
    float* Ps  = sm;                            // 32 x PS_LD
    int*  pxk  = (int*)(sm + 32 * PS_LD);       // 512
    int*  pyk  = pxk + 512;                     // 512
    int*  pxq  = pyk + 512;                     // 32
    int*  pyq  = pxq + 32;                      // 32
    float* db  = (float*)(pyq + 32);            // 32

    int q0 = blockIdx.x * 32;
    int h  = blockIdx.y;
    int b  = blockIdx.z;
    int tid = threadIdx.x;
    int w = tid >> 5, lane = tid & 31;

    for (int c = tid; c < 512; c += 256) { pxk[c] = px[b * NSEQ + c]; pyk[c] = py[b * NSEQ + c]; }
    if (tid < 32) {
        pxq[tid] = px[b * NSEQ + q0 + tid];
        pyq[tid] = py[b * NSEQ + q0 + tid];
        db[tid]  = demb[tid * HH + h];
    }

    wmma::fragment<wmma::accumulator, 16, 16, 8, float> acc[2][4];
    for (int mi = 0; mi < 2; mi++)
        for (int ni = 0; ni < 4; ni++) wmma::fill_fragment(acc[mi][ni], 0.0f);

    const float* qbase = q + ((size_t)(b * NSEQ + q0)) * DM + h * DK;
    const float* kbase = k + ((size_t)(b * NSEQ + w * 64)) * DM + h * DK;
    for (int kk = 0; kk < DK; kk += 8) {
        wmma::fragment<wmma::matrix_a, 16, 16, 8, wmma::precision::tf32, wmma::row_major> a[2];
        for (int mi = 0; mi < 2; mi++) {
            wmma::load_matrix_sync(a[mi], qbase + (size_t)mi * 16 * DM + kk, DM);
            for (int e = 0; e < a[mi].num_elements; e++) a[mi].x[e] = wmma::__float_to_tf32(a[mi].x[e]);
        }
        for (int ni = 0; ni < 4; ni++) {
            wmma::fragment<wmma::matrix_b, 16, 16, 8, wmma::precision::tf32, wmma::col_major> bfr;
            wmma::load_matrix_sync(bfr, kbase + (size_t)ni * 16 * DM + kk, DM);
            for (int e = 0; e < bfr.num_elements; e++) bfr.x[e] = wmma::__float_to_tf32(bfr.x[e]);
            for (int mi = 0; mi < 2; mi++) wmma::mma_sync(acc[mi][ni], a[mi], bfr, acc[mi][ni]);
        }
    }
    for (int mi = 0; mi < 2; mi++)
        for (int ni = 0; ni < 4; ni++) {
            for (int e = 0; e < acc[mi][ni].num_elements; e++) acc[mi][ni].x[e] *= 0.125f;
            wmma::store_matrix_sync(&Ps[(mi * 16) * PS_LD + w * 64 + ni * 16], acc[mi][ni],
                                    PS_LD, wmma::mem_row_major);
        }
    __syncthreads();

    float* attb = att + ((size_t)(b * HH + h) * NSEQ + q0) * NSEQ;
    for (int rr = 0; rr < 4; rr++) {
        int r = w * 4 + rr;
        int pxr = pxq[r], pyr = pyq[r];
        float mx = -1e30f;
        for (int c = lane; c < 512; c += 32) {
            int dx = pxk[c] - pxr, dy = pyk[c] - pyr;
            int bin = (int)(sqrtf((float)(dx * dx + dy * dy)) * 2.0f);
            float val = Ps[r * PS_LD + c] + db[bin];
            Ps[r * PS_LD + c] = val;
            mx = fmaxf(mx, val);
        }
        for (int o = 16; o; o >>= 1) mx = fmaxf(mx, __shfl_xor_sync(0xffffffffu, mx, o));
        float sum = 0.f;
        for (int c = lane; c < 512; c += 32) {
            float e = expf(Ps[r * PS_LD + c] - mx);
            Ps[r * PS_LD + c] = e;
            sum += e;
        }
        for (int o = 16; o; o >>= 1) sum += __shfl_xor_sync(0xffffffffu, sum, o);
        float inv = 1.0f / sum;
        for (int c = lane; c < 512; c += 32) {
            float p = Ps[r * PS_LD + c] * inv;
            Ps[r * PS_LD + c] = p;
            attb[(size_t)r * NSEQ + c] = p;
        }
    }
    __syncthreads();

    int mi = w >> 2, ni = w & 3;
    wmma::fragment<wmma::accumulator, 16, 16, 8, float> acc2;
    wmma::fill_fragment(acc2, 0.0f);
    const float* vbase = v + ((size_t)(b * NSEQ)) * DM + h * DK + ni * 16;
    for (int ks = 0; ks < 512; ks += 8) {
        wmma::fragment<wmma::matrix_a, 16, 16, 8, wmma::precision::tf32, wmma::row_major> a2;
        wmma::load_matrix_sync(a2, &Ps[(mi * 16) * PS_LD + ks], PS_LD);
        for (int e = 0; e < a2.num_elements; e++) a2.x[e] = wmma::__float_to_tf32(a2.x[e]);
        wmma::fragment<wmma::matrix_b, 16, 16, 8, wmma::precision::tf32, wmma::row_major> b2;
        wmma::load_matrix_sync(b2, vbase + (size_t)ks * DM, DM);
        for (int e = 0; e < b2.num_elements; e++) b2.x[e] = wmma::__float_to_tf32(b2.x[e]);
        wmma::mma_sync(acc2, a2, b2, acc2);
    }
    wmma::store_matrix_sync(oh + ((size_t)(b * NSEQ + q0 + mi * 16)) * DM + h * DK + ni * 16,
                            acc2, DM, wmma::mem_row_major);
}

// ---------------- launch ----------------
extern "C" void kernel_launch(void* const* d_in, const int* in_sizes, int n_in,
                              void* d_out, int out_size) {
    const float* features = (const float*)d_in[0];
    const float* boxes    = (const float*)d_in[1];
    const int*   img      = (const int*)d_in[2];
    const float* Wq = (const float*)d_in[3];  const float* bq = (const float*)d_in[4];
    const float* Wk = (const float*)d_in[5];  const float* bk = (const float*)d_in[6];
    const float* Wv = (const float*)d_in[7];  const float* bv = (const float*)d_in[8];
    const float* Wo = (const float*)d_in[9];  const float* bo = (const float*)d_in[10];
    const float* gamma = (const float*)d_in[11];
    const float* beta  = (const float*)d_in[12];
    const float* demb  = (const float*)d_in[13];

    float* out = (float*)d_out;                       // (B, N, D)
    float* att = out + (size_t)BB * NSEQ * DM;        // (B, H, N, N)

    float *xln, *qb, *kb, *vb, *ohb;
    int *pxp, *pyp;
    cudaGetSymbolAddress((void**)&xln, g_xln);
    cudaGetSymbolAddress((void**)&qb,  g_q);
    cudaGetSymbolAddress((void**)&kb,  g_k);
    cudaGetSymbolAddress((void**)&vb,  g_v);
    cudaGetSymbolAddress((void**)&ohb, g_oh);
    cudaGetSymbolAddress((void**)&pxp, g_px);
    cudaGetSymbolAddress((void**)&pyp, g_py);

    ln_kernel<<<MTOT, 256>>>(features, gamma, beta, xln);
    bins_kernel<<<(MTOT + 255) / 256, 256>>>(boxes, img, pxp, pyp);

    int gsmem = (2 * GBM * GLD + 2 * GBN * GLD) * 4;   // 73728 B
    cudaFuncSetAttribute(gemm_tf32_pipe, cudaFuncAttributeMaxDynamicSharedMemorySize, gsmem);

    // fused QKV: grid.z selects (W, bias, C)
    dim3 gqkv(DM / GBN, MTOT / GBM, 3);
    gemm_tf32_pipe<<<gqkv, 256, gsmem>>>(xln, Wq, Wk, Wv, bq, bk, bv, qb, kb, vb,
                                         MTOT, DM, DM);

    int smem = 32 * PS_LD * 4 + (512 * 2 + 32 * 2) * 4 + 32 * 4;
    cudaFuncSetAttribute(attn_kernel, cudaFuncAttributeMaxDynamicSharedMemorySize, smem);
    attn_kernel<<<dim3(NSEQ / 32, HH, BB), 256, smem>>>(qb, kb, vb, pxp, pyp, demb, att, ohb);

    dim3 go(DM / GBN, MTOT / GBM, 1);
    gemm_tf32_pipe<<<go, 256, gsmem>>>(ohb, Wo, Wo, Wo, bo, bo, bo, out, out, out,
                                       MTOT, DM, DM);
}

// round 10
// speedup vs baseline: 1.4812x; 1.0177x over previous
#include <cuda_runtime.h>
#include <mma.h>
#include <cstdint>
#include <cstdio>

using namespace nvcuda;

// Problem constants
#define BB   16
#define NSEQ 512
#define DM   768
#define HH   12
#define DK   64
#define NDE  32

#define MTOT (BB * NSEQ)   // 8192 rows

// ---------------- scratch (device globals; allocation-free) ----------------
__device__ float g_xln[MTOT * DM];
__device__ float g_q[MTOT * DM];     // head-major (B,H,N,DK)
__device__ float g_k[MTOT * DM];     // head-major
__device__ float g_v[MTOT * DM];     // head-major
__device__ float g_oh[MTOT * DM];    // token-major (B,N,D)
__device__ int   g_px[MTOT];
__device__ int   g_py[MTOT];

// ---------------- LayerNorm ----------------
__global__ __launch_bounds__(256) void ln_kernel(const float* __restrict__ x,
                                                 const float* __restrict__ gamma,
                                                 const float* __restrict__ beta,
                                                 float* __restrict__ y) {
    int row = blockIdx.x;
    int tid = threadIdx.x;
    const float* xr = x + (size_t)row * DM;
    float v0 = xr[tid], v1 = xr[tid + 256], v2 = xr[tid + 512];
    __shared__ float red[256];
    red[tid] = v0 + v1 + v2;
    __syncthreads();
    for (int o = 128; o; o >>= 1) { if (tid < o) red[tid] += red[tid + o]; __syncthreads(); }
    float mean = red[0] * (1.0f / 768.0f);
    __syncthreads();
    float d0 = v0 - mean, d1 = v1 - mean, d2 = v2 - mean;
    red[tid] = d0 * d0 + d1 * d1 + d2 * d2;
    __syncthreads();
    for (int o = 128; o; o >>= 1) { if (tid < o) red[tid] += red[tid + o]; __syncthreads(); }
    float rs = rsqrtf(red[0] * (1.0f / 768.0f) + 1e-5f);
    float* yr = y + (size_t)row * DM;
    yr[tid]       = d0 * rs * gamma[tid]       + beta[tid];
    yr[tid + 256] = d1 * rs * gamma[tid + 256] + beta[tid + 256];
    yr[tid + 512] = d2 * rs * gamma[tid + 512] + beta[tid + 512];
}

// ---------------- Patch bins ----------------
__global__ void bins_kernel(const float* __restrict__ boxes,
                            const int* __restrict__ img,
                            int* __restrict__ px, int* __restrict__ py) {
    int t = blockIdx.x * blockDim.x + threadIdx.x;
    if (t >= MTOT) return;
    int b = t / NSEQ;
    float wf = (float)img[b * 4 + 0];
    float hf = (float)img[b * 4 + 1];
    const float* bx = boxes + (size_t)t * 4;
    float spa_w = floorf(wf / 11.0f);
    float spa_h = floorf(hf / 11.0f);
    float cx = floorf((bx[0] * wf + bx[2] * wf) * 0.5f);
    float cy = floorf((bx[1] * hf + bx[3] * hf) * 0.5f);
    int pxi = 0, pyi = 0;
    for (int i = 0; i < 11; i++) {
        float lo = (float)i * spa_w, hi = (float)(i + 1) * spa_w;
        if (lo <= cx && cx <= hi) { pxi = i; break; }
    }
    for (int i = 0; i < 11; i++) {
        float lo = (float)i * spa_h, hi = (float)(i + 1) * spa_h;
        if (lo <= cy && cy <= hi) { pyi = i; break; }
    }
    px[t] = pxi;
    py[t] = pyi;
}

// ---------------- Pipelined TF32 GEMM: C = A @ W^T + bias ----------------
// headmajor != 0: output written as (B, H, N, DK) instead of (B*N, 768).
#define GBM 128
#define GBN 128
#define GBK 32
#define GLD 36

__device__ __forceinline__ void cp_async16(void* smem, const void* gmem) {
    uint32_t s = (uint32_t)__cvta_generic_to_shared(smem);
    asm volatile("cp.async.cg.shared.global [%0], [%1], 16;\n" :: "r"(s), "l"(gmem));
}

__global__ __launch_bounds__(256, 2) void gemm_tf32_pipe(
    const float* __restrict__ A,
    const float* __restrict__ W0, const float* __restrict__ W1, const float* __restrict__ W2,
    const float* __restrict__ b0, const float* __restrict__ b1, const float* __restrict__ b2,
    float* __restrict__ C0, float* __restrict__ C1, float* __restrict__ C2,
    int M, int Nn, int K, int headmajor)
{
    extern __shared__ float sm[];
    float* As = sm;                      // [2][GBM][GLD]
    float* Bs = sm + 2 * GBM * GLD;      // [2][GBN][GLD]

    const float* W    = blockIdx.z == 0 ? W0 : blockIdx.z == 1 ? W1 : W2;
    const float* bias = blockIdx.z == 0 ? b0 : blockIdx.z == 1 ? b1 : b2;
    float*       C    = blockIdx.z == 0 ? C0 : blockIdx.z == 1 ? C1 : C2;

    int tid = threadIdx.x;
    int w = tid >> 5, lane = tid & 31;
    int wm = w >> 2, wn = w & 3;
    int m0 = blockIdx.y * GBM;
    int n0 = blockIdx.x * GBN;

    wmma::fragment<wmma::accumulator, 16, 16, 8, float> acc[4][2];
    #pragma unroll
    for (int i = 0; i < 4; i++)
        #pragma unroll
        for (int j = 0; j < 2; j++) wmma::fill_fragment(acc[i][j], 0.0f);

    int r_ld  = tid >> 3;
    int c4_ld = (tid & 7) * 4;

    const int NIT = K / GBK;

    {
        float* Ab = As; float* Bb = Bs;
        #pragma unroll
        for (int j = 0; j < 4; j++) {
            int r = r_ld + j * 32;
            cp_async16(Ab + r * GLD + c4_ld, A + (size_t)(m0 + r) * K + c4_ld);
            cp_async16(Bb + r * GLD + c4_ld, W + (size_t)(n0 + r) * K + c4_ld);
        }
        asm volatile("cp.async.commit_group;\n" ::: "memory");
    }

    for (int it = 0; it < NIT; it++) {
        asm volatile("cp.async.wait_group 0;\n" ::: "memory");
        __syncthreads();
        if (it + 1 < NIT) {
            int k0 = (it + 1) * GBK;
            float* Ab = As + ((it + 1) & 1) * GBM * GLD;
            float* Bb = Bs + ((it + 1) & 1) * GBN * GLD;
            #pragma unroll
            for (int j = 0; j < 4; j++) {
                int r = r_ld + j * 32;
                cp_async16(Ab + r * GLD + c4_ld, A + (size_t)(m0 + r) * K + k0 + c4_ld);
                cp_async16(Bb + r * GLD + c4_ld, W + (size_t)(n0 + r) * K + k0 + c4_ld);
            }
            asm volatile("cp.async.commit_group;\n" ::: "memory");
        }
        float* Ab = As + (it & 1) * GBM * GLD;
        float* Bb = Bs + (it & 1) * GBN * GLD;
        #pragma unroll
        for (int ks = 0; ks < 4; ks++) {
            wmma::fragment<wmma::matrix_a, 16, 16, 8, wmma::precision::tf32, wmma::row_major> af[4];
            wmma::fragment<wmma::matrix_b, 16, 16, 8, wmma::precision::tf32, wmma::col_major> bf[2];
            #pragma unroll
            for (int mi = 0; mi < 4; mi++) {
                wmma::load_matrix_sync(af[mi], Ab + (wm * 64 + mi * 16) * GLD + ks * 8, GLD);
                #pragma unroll
                for (int e = 0; e < af[mi].num_elements; e++)
                    af[mi].x[e] = wmma::__float_to_tf32(af[mi].x[e]);
            }
            #pragma unroll
            for (int ni = 0; ni < 2; ni++) {
                wmma::load_matrix_sync(bf[ni], Bb + (wn * 32 + ni * 16) * GLD + ks * 8, GLD);
                #pragma unroll
                for (int e = 0; e < bf[ni].num_elements; e++)
                    bf[ni].x[e] = wmma::__float_to_tf32(bf[ni].x[e]);
            }
            #pragma unroll
            for (int mi = 0; mi < 4; mi++)
                #pragma unroll
                for (int ni = 0; ni < 2; ni++)
                    wmma::mma_sync(acc[mi][ni], af[mi], bf[ni], acc[mi][ni]);
        }
        __syncthreads();
    }

    // epilogue
    float* stg = sm + w * (16 * 20);
    #pragma unroll
    for (int mi = 0; mi < 4; mi++)
        #pragma unroll
        for (int ni = 0; ni < 2; ni++) {
            wmma::store_matrix_sync(stg, acc[mi][ni], 20, wmma::mem_row_major);
            __syncwarp();
            int r0 = m0 + wm * 64 + mi * 16;
            int c0 = n0 + wn * 32 + ni * 16;
            if (headmajor) {
                // output (B,H,N,DK): row -> (b, n); col -> (h, d). 16-wide tile never crosses a head.
                int h = c0 >> 6, dbase = c0 & 63;
                #pragma unroll
                for (int e = lane; e < 256; e += 32) {
                    int r = e >> 4, c = e & 15;
                    int grow = r0 + r;
                    int bb_ = grow >> 9, nn_ = grow & 511;
                    C[(((size_t)bb_ * HH + h) * NSEQ + nn_) * DK + dbase + c] =
                        stg[r * 20 + c] + bias[c0 + c];
                }
            } else {
                #pragma unroll
                for (int e = lane; e < 256; e += 32) {
                    int r = e >> 4, c = e & 15;
                    C[(size_t)(r0 + r) * Nn + c0 + c] = stg[r * 20 + c] + bias[c0 + c];
                }
            }
            __syncwarp();
        }
}

// ---------------- Fused attention (head-major q/k/v) ----------------
#define PS_LD 520
#define RLD 36    // reduce-staging leading dim

__global__ __launch_bounds__(256, 2) void attn_kernel(const float* __restrict__ q,
                                                      const float* __restrict__ k,
                                                      const float* __restrict__ v,
                                                      const int* __restrict__ px,
                                                      const int* __restrict__ py,
                                                      const float* __restrict__ demb,
                                                      float* __restrict__ att,
                                                      float* __restrict__ oh) {
    extern __shared__ float sm[];
    float* Ps  = sm;                            // 32 x PS_LD (scores / P; later reduce staging)
    int*  pxk  = (int*)(sm + 32 * PS_LD);       // 512
    int*  pyk  = pxk + 512;                     // 512
    int*  pxq  = pyk + 512;                     // 32
    int*  pyq  = pxq + 32;                      // 32
    float* db  = (float*)(pyq + 32);            // 32

    int q0 = blockIdx.x * 32;
    int h  = blockIdx.y;
    int b  = blockIdx.z;
    int tid = threadIdx.x;
    int w = tid >> 5, lane = tid & 31;

    for (int c = tid; c < 512; c += 256) { pxk[c] = px[b * NSEQ + c]; pyk[c] = py[b * NSEQ + c]; }
    if (tid < 32) {
        pxq[tid] = px[b * NSEQ + q0 + tid];
        pyq[tid] = py[b * NSEQ + q0 + tid];
        db[tid]  = demb[tid * HH + h];
    }

    const float* qh = q + ((size_t)(b * HH + h) * NSEQ) * DK;   // [512][64]
    const float* kh = k + ((size_t)(b * HH + h) * NSEQ) * DK;
    const float* vh = v + ((size_t)(b * HH + h) * NSEQ) * DK;

    // ---- S = Q K^T (warp w covers keys [w*64, w*64+64)) ----
    wmma::fragment<wmma::accumulator, 16, 16, 8, float> acc[2][4];
    #pragma unroll
    for (int mi = 0; mi < 2; mi++)
        #pragma unroll
        for (int ni = 0; ni < 4; ni++) wmma::fill_fragment(acc[mi][ni], 0.0f);

    const float* qbase = qh + (size_t)q0 * DK;
    const float* kbase = kh + (size_t)(w * 64) * DK;
    #pragma unroll
    for (int kk = 0; kk < DK; kk += 8) {
        wmma::fragment<wmma::matrix_a, 16, 16, 8, wmma::precision::tf32, wmma::row_major> a[2];
        #pragma unroll
        for (int mi = 0; mi < 2; mi++) {
            wmma::load_matrix_sync(a[mi], qbase + (size_t)mi * 16 * DK + kk, DK);
            #pragma unroll
            for (int e = 0; e < a[mi].num_elements; e++) a[mi].x[e] = wmma::__float_to_tf32(a[mi].x[e]);
        }
        #pragma unroll
        for (int ni = 0; ni < 4; ni++) {
            wmma::fragment<wmma::matrix_b, 16, 16, 8, wmma::precision::tf32, wmma::col_major> bfr;
            wmma::load_matrix_sync(bfr, kbase + (size_t)ni * 16 * DK + kk, DK);
            #pragma unroll
            for (int e = 0; e < bfr.num_elements; e++) bfr.x[e] = wmma::__float_to_tf32(bfr.x[e]);
            #pragma unroll
            for (int mi = 0; mi < 2; mi++) wmma::mma_sync(acc[mi][ni], a[mi], bfr, acc[mi][ni]);
        }
    }
    #pragma unroll
    for (int mi = 0; mi < 2; mi++)
        #pragma unroll
        for (int ni = 0; ni < 4; ni++) {
            #pragma unroll
            for (int e = 0; e < acc[mi][ni].num_elements; e++) acc[mi][ni].x[e] *= 0.125f;
            wmma::store_matrix_sync(&Ps[(mi * 16) * PS_LD + w * 64 + ni * 16], acc[mi][ni],
                                    PS_LD, wmma::mem_row_major);
        }
    __syncthreads();

    // ---- bias + softmax; write att ----
    float* attb = att + ((size_t)(b * HH + h) * NSEQ + q0) * NSEQ;
    for (int rr = 0; rr < 4; rr++) {
        int r = w * 4 + rr;
        int pxr = pxq[r], pyr = pyq[r];
        float mx = -1e30f;
        for (int c = lane; c < 512; c += 32) {
            int dx = pxk[c] - pxr, dy = pyk[c] - pyr;
            int bin = (int)(sqrtf((float)(dx * dx + dy * dy)) * 2.0f);
            float val = Ps[r * PS_LD + c] + db[bin];
            Ps[r * PS_LD + c] = val;
            mx = fmaxf(mx, val);
        }
        for (int o = 16; o; o >>= 1) mx = fmaxf(mx, __shfl_xor_sync(0xffffffffu, mx, o));
        float sum = 0.f;
        for (int c = lane; c < 512; c += 32) {
            float e = expf(Ps[r * PS_LD + c] - mx);
            Ps[r * PS_LD + c] = e;
            sum += e;
        }
        for (int o = 16; o; o >>= 1) sum += __shfl_xor_sync(0xffffffffu, sum, o);
        float inv = 1.0f / sum;
        for (int c = lane; c < 512; c += 32) {
            float p = Ps[r * PS_LD + c] * inv;
            Ps[r * PS_LD + c] = p;
            attb[(size_t)r * NSEQ + c] = p;
        }
    }
    __syncthreads();

    // ---- out = P V, split-K across warps ----
    // warp w: khalf = w>>2, q_mi = (w>>1)&1, n_pair = w&1  (cols n_pair*32..+31)
    int khalf = w >> 2, q_mi = (w >> 1) & 1, n_pair = w & 1;
    wmma::fragment<wmma::accumulator, 16, 16, 8, float> acc2[2];
    wmma::fill_fragment(acc2[0], 0.0f);
    wmma::fill_fragment(acc2[1], 0.0f);
    const float* vb0 = vh + (size_t)n_pair * 32;
    int ks0 = khalf * 256;
    for (int ks = ks0; ks < ks0 + 256; ks += 8) {
        wmma::fragment<wmma::matrix_a, 16, 16, 8, wmma::precision::tf32, wmma::row_major> a2;
        wmma::load_matrix_sync(a2, &Ps[(q_mi * 16) * PS_LD + ks], PS_LD);
        #pragma unroll
        for (int e = 0; e < a2.num_elements; e++) a2.x[e] = wmma::__float_to_tf32(a2.x[e]);
        #pragma unroll
        for (int ni = 0; ni < 2; ni++) {
            wmma::fragment<wmma::matrix_b, 16, 16, 8, wmma::precision::tf32, wmma::row_major> b2;
            wmma::load_matrix_sync(b2, vb0 + (size_t)ks * DK + ni * 16, DK);
            #pragma unroll
            for (int e = 0; e < b2.num_elements; e++) b2.x[e] = wmma::__float_to_tf32(b2.x[e]);
            wmma::mma_sync(acc2[ni], a2, b2, acc2[ni]);
        }
    }
    __syncthreads();   // all warps done reading Ps (P values)

    // stage partial 16x32 tiles into Ps region: warp w -> Ps + w*16*RLD
    {
        float* red = Ps + w * (16 * RLD);
        wmma::store_matrix_sync(red,      acc2[0], RLD, wmma::mem_row_major);
        wmma::store_matrix_sync(red + 16, acc2[1], RLD, wmma::mem_row_major);
    }
    __syncthreads();

    // reduce two k-halves and write oh (token-major, B,N,768)
    for (int idx = tid; idx < 32 * 64; idx += 256) {
        int qq = idx >> 6, dd = idx & 63;
        int t = ((qq >> 4) << 1) | (dd >> 5);             // tile id 0..3
        int rr = qq & 15, cc = dd & 31;
        float val = Ps[t * (16 * RLD) + rr * RLD + cc] +
                    Ps[(4 + t) * (16 * RLD) + rr * RLD + cc];
        oh[((size_t)(b * NSEQ + q0 + qq)) * DM + h * DK + dd] = val;
    }
}

// ---------------- launch ----------------
extern "C" void kernel_launch(void* const* d_in, const int* in_sizes, int n_in,
                              void* d_out, int out_size) {
    const float* features = (const float*)d_in[0];
    const float* boxes    = (const float*)d_in[1];
    const int*   img      = (const int*)d_in[2];
    const float* Wq = (const float*)d_in[3];  const float* bq = (const float*)d_in[4];
    const float* Wk = (const float*)d_in[5];  const float* bk = (const float*)d_in[6];
    const float* Wv = (const float*)d_in[7];  const float* bv = (const float*)d_in[8];
    const float* Wo = (const float*)d_in[9];  const float* bo = (const float*)d_in[10];
    const float* gamma = (const float*)d_in[11];
    const float* beta  = (const float*)d_in[12];
    const float* demb  = (const float*)d_in[13];

    float* out = (float*)d_out;                       // (B, N, D)
    float* att = out + (size_t)BB * NSEQ * DM;        // (B, H, N, N)

    float *xln, *qb, *kb, *vb, *ohb;
    int *pxp, *pyp;
    cudaGetSymbolAddress((void**)&xln, g_xln);
    cudaGetSymbolAddress((void**)&qb,  g_q);
    cudaGetSymbolAddress((void**)&kb,  g_k);
    cudaGetSymbolAddress((void**)&vb,  g_v);
    cudaGetSymbolAddress((void**)&ohb, g_oh);
    cudaGetSymbolAddress((void**)&pxp, g_px);
    cudaGetSymbolAddress((void**)&pyp, g_py);

    ln_kernel<<<MTOT, 256>>>(features, gamma, beta, xln);
    bins_kernel<<<(MTOT + 255) / 256, 256>>>(boxes, img, pxp, pyp);

    int gsmem = (2 * GBM * GLD + 2 * GBN * GLD) * 4;   // 73728 B
    cudaFuncSetAttribute(gemm_tf32_pipe, cudaFuncAttributeMaxDynamicSharedMemorySize, gsmem);

    // fused QKV (head-major outputs)
    dim3 gqkv(DM / GBN, MTOT / GBM, 3);
    gemm_tf32_pipe<<<gqkv, 256, gsmem>>>(xln, Wq, Wk, Wv, bq, bk, bv, qb, kb, vb,
                                         MTOT, DM, DM, 1);

    int smem = 32 * PS_LD * 4 + (512 * 2 + 32 * 2) * 4 + 32 * 4;
    cudaFuncSetAttribute(attn_kernel, cudaFuncAttributeMaxDynamicSharedMemorySize, smem);
    attn_kernel<<<dim3(NSEQ / 32, HH, BB), 256, smem>>>(qb, kb, vb, pxp, pyp, demb, att, ohb);

    dim3 go(DM / GBN, MTOT / GBM, 1);
    gemm_tf32_pipe<<<go, 256, gsmem>>>(ohb, Wo, Wo, Wo, bo, bo, bo, out, out, out,
                                       MTOT, DM, DM, 0);
}

// round 11
// speedup vs baseline: 1.5926x; 1.0752x over previous
#include <cuda_runtime.h>
#include <mma.h>
#include <cstdint>
#include <cstdio>

using namespace nvcuda;

// Problem constants
#define BB   16
#define NSEQ 512
#define DM   768
#define HH   12
#define DK   64
#define NDE  32

#define MTOT (BB * NSEQ)   // 8192 rows

// ---------------- scratch (device globals; allocation-free) ----------------
__device__ float g_xln[MTOT * DM];
__device__ float g_q[MTOT * DM];     // head-major (B,H,N,DK)
__device__ float g_k[MTOT * DM];     // head-major
__device__ float g_v[MTOT * DM];     // head-major
__device__ float g_oh[MTOT * DM];    // token-major (B,N,D)
__device__ int   g_px[MTOT];
__device__ int   g_py[MTOT];

// ---------------- LayerNorm ----------------
__global__ __launch_bounds__(256) void ln_kernel(const float* __restrict__ x,
                                                 const float* __restrict__ gamma,
                                                 const float* __restrict__ beta,
                                                 float* __restrict__ y) {
    int row = blockIdx.x;
    int tid = threadIdx.x;
    const float* xr = x + (size_t)row * DM;
    float v0 = xr[tid], v1 = xr[tid + 256], v2 = xr[tid + 512];
    __shared__ float red[256];
    red[tid] = v0 + v1 + v2;
    __syncthreads();
    for (int o = 128; o; o >>= 1) { if (tid < o) red[tid] += red[tid + o]; __syncthreads(); }
    float mean = red[0] * (1.0f / 768.0f);
    __syncthreads();
    float d0 = v0 - mean, d1 = v1 - mean, d2 = v2 - mean;
    red[tid] = d0 * d0 + d1 * d1 + d2 * d2;
    __syncthreads();
    for (int o = 128; o; o >>= 1) { if (tid < o) red[tid] += red[tid + o]; __syncthreads(); }
    float rs = rsqrtf(red[0] * (1.0f / 768.0f) + 1e-5f);
    float* yr = y + (size_t)row * DM;
    yr[tid]       = d0 * rs * gamma[tid]       + beta[tid];
    yr[tid + 256] = d1 * rs * gamma[tid + 256] + beta[tid + 256];
    yr[tid + 512] = d2 * rs * gamma[tid + 512] + beta[tid + 512];
}

// ---------------- Patch bins ----------------
__global__ void bins_kernel(const float* __restrict__ boxes,
                            const int* __restrict__ img,
                            int* __restrict__ px, int* __restrict__ py) {
    int t = blockIdx.x * blockDim.x + threadIdx.x;
    if (t >= MTOT) return;
    int b = t / NSEQ;
    float wf = (float)img[b * 4 + 0];
    float hf = (float)img[b * 4 + 1];
    const float* bx = boxes + (size_t)t * 4;
    float spa_w = floorf(wf / 11.0f);
    float spa_h = floorf(hf / 11.0f);
    float cx = floorf((bx[0] * wf + bx[2] * wf) * 0.5f);
    float cy = floorf((bx[1] * hf + bx[3] * hf) * 0.5f);
    int pxi = 0, pyi = 0;
    for (int i = 0; i < 11; i++) {
        float lo = (float)i * spa_w, hi = (float)(i + 1) * spa_w;
        if (lo <= cx && cx <= hi) { pxi = i; break; }
    }
    for (int i = 0; i < 11; i++) {
        float lo = (float)i * spa_h, hi = (float)(i + 1) * spa_h;
        if (lo <= cy && cy <= hi) { pyi = i; break; }
    }
    px[t] = pxi;
    py[t] = pyi;
}

// ---------------- Pipelined TF32 GEMM: C = A @ W^T + bias ----------------
#define GBM 128
#define GBN 128
#define GBK 32
#define GLD 36

__device__ __forceinline__ void cp_async16(void* smem, const void* gmem) {
    uint32_t s = (uint32_t)__cvta_generic_to_shared(smem);
    asm volatile("cp.async.cg.shared.global [%0], [%1], 16;\n" :: "r"(s), "l"(gmem));
}

__global__ __launch_bounds__(256, 2) void gemm_tf32_pipe(
    const float* __restrict__ A,
    const float* __restrict__ W0, const float* __restrict__ W1, const float* __restrict__ W2,
    const float* __restrict__ b0, const float* __restrict__ b1, const float* __restrict__ b2,
    float* __restrict__ C0, float* __restrict__ C1, float* __restrict__ C2,
    int M, int Nn, int K, int headmajor)
{
    extern __shared__ float sm[];
    float* As = sm;
    float* Bs = sm + 2 * GBM * GLD;

    const float* W    = blockIdx.z == 0 ? W0 : blockIdx.z == 1 ? W1 : W2;
    const float* bias = blockIdx.z == 0 ? b0 : blockIdx.z == 1 ? b1 : b2;
    float*       C    = blockIdx.z == 0 ? C0 : blockIdx.z == 1 ? C1 : C2;

    int tid = threadIdx.x;
    int w = tid >> 5, lane = tid & 31;
    int wm = w >> 2, wn = w & 3;
    int m0 = blockIdx.y * GBM;
    int n0 = blockIdx.x * GBN;

    wmma::fragment<wmma::accumulator, 16, 16, 8, float> acc[4][2];
    #pragma unroll
    for (int i = 0; i < 4; i++)
        #pragma unroll
        for (int j = 0; j < 2; j++) wmma::fill_fragment(acc[i][j], 0.0f);

    int r_ld  = tid >> 3;
    int c4_ld = (tid & 7) * 4;

    const int NIT = K / GBK;

    {
        float* Ab = As; float* Bb = Bs;
        #pragma unroll
        for (int j = 0; j < 4; j++) {
            int r = r_ld + j * 32;
            cp_async16(Ab + r * GLD + c4_ld, A + (size_t)(m0 + r) * K + c4_ld);
            cp_async16(Bb + r * GLD + c4_ld, W + (size_t)(n0 + r) * K + c4_ld);
        }
        asm volatile("cp.async.commit_group;\n" ::: "memory");
    }

    for (int it = 0; it < NIT; it++) {
        asm volatile("cp.async.wait_group 0;\n" ::: "memory");
        __syncthreads();
        if (it + 1 < NIT) {
            int k0 = (it + 1) * GBK;
            float* Ab = As + ((it + 1) & 1) * GBM * GLD;
            float* Bb = Bs + ((it + 1) & 1) * GBN * GLD;
            #pragma unroll
            for (int j = 0; j < 4; j++) {
                int r = r_ld + j * 32;
                cp_async16(Ab + r * GLD + c4_ld, A + (size_t)(m0 + r) * K + k0 + c4_ld);
                cp_async16(Bb + r * GLD + c4_ld, W + (size_t)(n0 + r) * K + k0 + c4_ld);
            }
            asm volatile("cp.async.commit_group;\n" ::: "memory");
        }
        float* Ab = As + (it & 1) * GBM * GLD;
        float* Bb = Bs + (it & 1) * GBN * GLD;
        #pragma unroll
        for (int ks = 0; ks < 4; ks++) {
            wmma::fragment<wmma::matrix_a, 16, 16, 8, wmma::precision::tf32, wmma::row_major> af[4];
            wmma::fragment<wmma::matrix_b, 16, 16, 8, wmma::precision::tf32, wmma::col_major> bf[2];
            #pragma unroll
            for (int mi = 0; mi < 4; mi++) {
                wmma::load_matrix_sync(af[mi], Ab + (wm * 64 + mi * 16) * GLD + ks * 8, GLD);
                #pragma unroll
                for (int e = 0; e < af[mi].num_elements; e++)
                    af[mi].x[e] = wmma::__float_to_tf32(af[mi].x[e]);
            }
            #pragma unroll
            for (int ni = 0; ni < 2; ni++) {
                wmma::load_matrix_sync(bf[ni], Bb + (wn * 32 + ni * 16) * GLD + ks * 8, GLD);
                #pragma unroll
                for (int e = 0; e < bf[ni].num_elements; e++)
                    bf[ni].x[e] = wmma::__float_to_tf32(bf[ni].x[e]);
            }
            #pragma unroll
            for (int mi = 0; mi < 4; mi++)
                #pragma unroll
                for (int ni = 0; ni < 2; ni++)
                    wmma::mma_sync(acc[mi][ni], af[mi], bf[ni], acc[mi][ni]);
        }
        __syncthreads();
    }

    float* stg = sm + w * (16 * 20);
    #pragma unroll
    for (int mi = 0; mi < 4; mi++)
        #pragma unroll
        for (int ni = 0; ni < 2; ni++) {
            wmma::store_matrix_sync(stg, acc[mi][ni], 20, wmma::mem_row_major);
            __syncwarp();
            int r0 = m0 + wm * 64 + mi * 16;
            int c0 = n0 + wn * 32 + ni * 16;
            if (headmajor) {
                int h = c0 >> 6, dbase = c0 & 63;
                #pragma unroll
                for (int e = lane; e < 256; e += 32) {
                    int r = e >> 4, c = e & 15;
                    int grow = r0 + r;
                    int bb_ = grow >> 9, nn_ = grow & 511;
                    C[(((size_t)bb_ * HH + h) * NSEQ + nn_) * DK + dbase + c] =
                        stg[r * 20 + c] + bias[c0 + c];
                }
            } else {
                #pragma unroll
                for (int e = lane; e < 256; e += 32) {
                    int r = e >> 4, c = e & 15;
                    C[(size_t)(r0 + r) * Nn + c0 + c] = stg[r * 20 + c] + bias[c0 + c];
                }
            }
            __syncwarp();
        }
}

// ---------------- Fused attention v2: SMEM-staged, conflict-free frag ops ----------------
// 32 queries x 512 keys per CTA, one (b,h). 8 warps / 256 threads, 2 CTA/SM.
// K/V processed in 4 chunks of 128 keys staged via cp.async into one buffer.
#define PLD 516   // Ps leading dim: 516 mod 32 = 4 -> frag ops conflict-free
#define QLD 68    // Q / output staging leading dim (68 mod 32 = 4)
#define KLD 68    // K/V chunk leading dim

__global__ __launch_bounds__(256, 2) void attn_kernel(const float* __restrict__ q,
                                                      const float* __restrict__ k,
                                                      const float* __restrict__ v,
                                                      const int* __restrict__ px,
                                                      const int* __restrict__ py,
                                                      const float* __restrict__ demb,
                                                      float* __restrict__ att,
                                                      float* __restrict__ oh) {
    extern __shared__ float sm[];
    float* Ps   = sm;                               // [32][PLD]
    float* Qs   = sm + 32 * PLD;                    // [32][QLD]  (later: output staging)
    float* KVs  = Qs + 32 * QLD;                    // [128][KLD]
    int*   pxyk = (int*)(KVs + 128 * KLD);          // [512] packed px|py<<16
    int*   pxyq = pxyk + 512;                       // [32]
    float* db2  = (float*)(pxyq + 32);              // [441] bias lookup by (dx+10, dy+10)

    int q0 = blockIdx.x * 32;
    int h  = blockIdx.y;
    int b  = blockIdx.z;
    int tid = threadIdx.x;
    int w = tid >> 5, lane = tid & 31;

    const float* qh = q + ((size_t)(b * HH + h) * NSEQ) * DK;   // [512][64]
    const float* kh = k + ((size_t)(b * HH + h) * NSEQ) * DK;
    const float* vh = v + ((size_t)(b * HH + h) * NSEQ) * DK;

    // ---- stage Q (coalesced float4 cp.async) + bins + bias table ----
    for (int i = tid; i < 32 * 16; i += 256) {
        int r = i >> 4, c4 = i & 15;
        cp_async16(Qs + r * QLD + c4 * 4, qh + (size_t)(q0 + r) * DK + c4 * 4);
    }
    asm volatile("cp.async.commit_group;\n" ::: "memory");

    for (int c = tid; c < 512; c += 256)
        pxyk[c] = px[b * NSEQ + c] | (py[b * NSEQ + c] << 16);
    if (tid < 32)
        pxyq[tid] = px[b * NSEQ + q0 + tid] | (py[b * NSEQ + q0 + tid] << 16);
    for (int i = tid; i < 441; i += 256) {
        int dx = i / 21 - 10, dy = i % 21 - 10;
        int bin = (int)(sqrtf((float)(dx * dx + dy * dy)) * 2.0f);
        db2[i] = demb[bin * HH + h];
    }

    // ---- S = Q K^T in 4 key-chunks of 128 ----
    int wq = w >> 2, wk = w & 3;     // 2 q-tiles x 4 key-subtiles
    for (int ch = 0; ch < 4; ch++) {
        for (int i = tid; i < 128 * 16; i += 256) {
            int r = i >> 4, c4 = i & 15;
            cp_async16(KVs + r * KLD + c4 * 4, kh + (size_t)(ch * 128 + r) * DK + c4 * 4);
        }
        asm volatile("cp.async.commit_group;\n" ::: "memory");
        asm volatile("cp.async.wait_group 0;\n" ::: "memory");
        __syncthreads();

        wmma::fragment<wmma::accumulator, 16, 16, 8, float> acc[2];
        wmma::fill_fragment(acc[0], 0.0f);
        wmma::fill_fragment(acc[1], 0.0f);
        #pragma unroll
        for (int kk = 0; kk < DK; kk += 8) {
            wmma::fragment<wmma::matrix_a, 16, 16, 8, wmma::precision::tf32, wmma::row_major> af;
            wmma::load_matrix_sync(af, Qs + (wq * 16) * QLD + kk, QLD);
            #pragma unroll
            for (int e = 0; e < af.num_elements; e++) af.x[e] = wmma::__float_to_tf32(af.x[e]);
            #pragma unroll
            for (int ni = 0; ni < 2; ni++) {
                wmma::fragment<wmma::matrix_b, 16, 16, 8, wmma::precision::tf32, wmma::col_major> bf;
                wmma::load_matrix_sync(bf, KVs + (wk * 32 + ni * 16) * KLD + kk, KLD);
                #pragma unroll
                for (int e = 0; e < bf.num_elements; e++) bf.x[e] = wmma::__float_to_tf32(bf.x[e]);
                wmma::mma_sync(acc[ni], af, bf, acc[ni]);
            }
        }
        #pragma unroll
        for (int ni = 0; ni < 2; ni++) {
            #pragma unroll
            for (int e = 0; e < acc[ni].num_elements; e++) acc[ni].x[e] *= 0.125f;
            wmma::store_matrix_sync(&Ps[(wq * 16) * PLD + ch * 128 + wk * 32 + ni * 16],
                                    acc[ni], PLD, wmma::mem_row_major);
        }
        __syncthreads();    // all warps done with KVs before next chunk overwrites
    }

    // ---- bias + softmax (vectorized float4, __expf), write att ----
    float* attb = att + ((size_t)(b * HH + h) * NSEQ + q0) * NSEQ;
    for (int rr = 0; rr < 4; rr++) {
        int r = w * 4 + rr;
        int pq = pxyq[r];
        int pxr = pq & 0xffff, pyr = pq >> 16;
        float mx = -1e30f;
        #pragma unroll
        for (int i = 0; i < 4; i++) {
            int c0 = i * 128 + lane * 4;
            float4 s = *(float4*)&Ps[r * PLD + c0];
            int4 pk = *(int4*)&pxyk[c0];
            s.x += db2[((pk.x & 0xffff) - pxr + 10) * 21 + ((pk.x >> 16) - pyr + 10)];
            s.y += db2[((pk.y & 0xffff) - pxr + 10) * 21 + ((pk.y >> 16) - pyr + 10)];
            s.z += db2[((pk.z & 0xffff) - pxr + 10) * 21 + ((pk.z >> 16) - pyr + 10)];
            s.w += db2[((pk.w & 0xffff) - pxr + 10) * 21 + ((pk.w >> 16) - pyr + 10)];
            *(float4*)&Ps[r * PLD + c0] = s;
            mx = fmaxf(mx, fmaxf(fmaxf(s.x, s.y), fmaxf(s.z, s.w)));
        }
        #pragma unroll
        for (int o = 16; o; o >>= 1) mx = fmaxf(mx, __shfl_xor_sync(0xffffffffu, mx, o));
        float sum = 0.f;
        #pragma unroll
        for (int i = 0; i < 4; i++) {
            int c0 = i * 128 + lane * 4;
            float4 s = *(float4*)&Ps[r * PLD + c0];
            s.x = __expf(s.x - mx); s.y = __expf(s.y - mx);
            s.z = __expf(s.z - mx); s.w = __expf(s.w - mx);
            *(float4*)&Ps[r * PLD + c0] = s;
            sum += s.x + s.y + s.z + s.w;
        }
        #pragma unroll
        for (int o = 16; o; o >>= 1) sum += __shfl_xor_sync(0xffffffffu, sum, o);
        float inv = 1.0f / sum;
        #pragma unroll
        for (int i = 0; i < 4; i++) {
            int c0 = i * 128 + lane * 4;
            float4 s = *(float4*)&Ps[r * PLD + c0];
            s.x *= inv; s.y *= inv; s.z *= inv; s.w *= inv;
            *(float4*)&Ps[r * PLD + c0] = s;
            *(float4*)&attb[(size_t)r * NSEQ + c0] = s;
        }
    }
    __syncthreads();

    // ---- out = P V in 4 key-chunks (V staged into KVs) ----
    int q_mi = w >> 2, n_i = w & 3;   // 2 q-tiles x 4 n-tiles of 16x16
    wmma::fragment<wmma::accumulator, 16, 16, 8, float> acc2;
    wmma::fill_fragment(acc2, 0.0f);
    for (int ch = 0; ch < 4; ch++) {
        for (int i = tid; i < 128 * 16; i += 256) {
            int r = i >> 4, c4 = i & 15;
            cp_async16(KVs + r * KLD + c4 * 4, vh + (size_t)(ch * 128 + r) * DK + c4 * 4);
        }
        asm volatile("cp.async.commit_group;\n" ::: "memory");
        asm volatile("cp.async.wait_group 0;\n" ::: "memory");
        __syncthreads();
        #pragma unroll
        for (int kk = 0; kk < 128; kk += 8) {
            wmma::fragment<wmma::matrix_a, 16, 16, 8, wmma::precision::tf32, wmma::row_major> a2;
            wmma::load_matrix_sync(a2, &Ps[(q_mi * 16) * PLD + ch * 128 + kk], PLD);
            #pragma unroll
            for (int e = 0; e < a2.num_elements; e++) a2.x[e] = wmma::__float_to_tf32(a2.x[e]);
            wmma::fragment<wmma::matrix_b, 16, 16, 8, wmma::precision::tf32, wmma::row_major> b2;
            wmma::load_matrix_sync(b2, KVs + kk * KLD + n_i * 16, KLD);
            #pragma unroll
            for (int e = 0; e < b2.num_elements; e++) b2.x[e] = wmma::__float_to_tf32(b2.x[e]);
            wmma::mma_sync(acc2, a2, b2, acc2);
        }
        __syncthreads();
    }

    // ---- epilogue: stage 32x64 output in Qs, coalesced float4 write to oh ----
    wmma::store_matrix_sync(Qs + (q_mi * 16) * QLD + n_i * 16, acc2, QLD, wmma::mem_row_major);
    __syncthreads();
    for (int i = tid; i < 512; i += 256) {
        int r = i >> 4, c4 = i & 15;
        float4 val = *(float4*)&Qs[r * QLD + c4 * 4];
        *(float4*)&oh[((size_t)(b * NSEQ + q0 + r)) * DM + h * DK + c4 * 4] = val;
    }
}

// ---------------- launch ----------------
extern "C" void kernel_launch(void* const* d_in, const int* in_sizes, int n_in,
                              void* d_out, int out_size) {
    const float* features = (const float*)d_in[0];
    const float* boxes    = (const float*)d_in[1];
    const int*   img      = (const int*)d_in[2];
    const float* Wq = (const float*)d_in[3];  const float* bq = (const float*)d_in[4];
    const float* Wk = (const float*)d_in[5];  const float* bk = (const float*)d_in[6];
    const float* Wv = (const float*)d_in[7];  const float* bv = (const float*)d_in[8];
    const float* Wo = (const float*)d_in[9];  const float* bo = (const float*)d_in[10];
    const float* gamma = (const float*)d_in[11];
    const float* beta  = (const float*)d_in[12];
    const float* demb  = (const float*)d_in[13];

    float* out = (float*)d_out;                       // (B, N, D)
    float* att = out + (size_t)BB * NSEQ * DM;        // (B, H, N, N)

    float *xln, *qb, *kb, *vb, *ohb;
    int *pxp, *pyp;
    cudaGetSymbolAddress((void**)&xln, g_xln);
    cudaGetSymbolAddress((void**)&qb,  g_q);
    cudaGetSymbolAddress((void**)&kb,  g_k);
    cudaGetSymbolAddress((void**)&vb,  g_v);
    cudaGetSymbolAddress((void**)&ohb, g_oh);
    cudaGetSymbolAddress((void**)&pxp, g_px);
    cudaGetSymbolAddress((void**)&pyp, g_py);

    ln_kernel<<<MTOT, 256>>>(features, gamma, beta, xln);
    bins_kernel<<<(MTOT + 255) / 256, 256>>>(boxes, img, pxp, pyp);

    int gsmem = (2 * GBM * GLD + 2 * GBN * GLD) * 4;   // 73728 B
    cudaFuncSetAttribute(gemm_tf32_pipe, cudaFuncAttributeMaxDynamicSharedMemorySize, gsmem);

    // fused QKV (head-major outputs)
    dim3 gqkv(DM / GBN, MTOT / GBM, 3);
    gemm_tf32_pipe<<<gqkv, 256, gsmem>>>(xln, Wq, Wk, Wv, bq, bk, bv, qb, kb, vb,
                                         MTOT, DM, DM, 1);

    int asmem = (32 * PLD + 32 * QLD + 128 * KLD) * 4 + 512 * 4 + 32 * 4 + 441 * 4;
    cudaFuncSetAttribute(attn_kernel, cudaFuncAttributeMaxDynamicSharedMemorySize, asmem);
    attn_kernel<<<dim3(NSEQ / 32, HH, BB), 256, asmem>>>(qb, kb, vb, pxp, pyp, demb, att, ohb);

    dim3 go(DM / GBN, MTOT / GBM, 1);
    gemm_tf32_pipe<<<go, 256, gsmem>>>(ohb, Wo, Wo, Wo, bo, bo, bo, out, out, out,
                                       MTOT, DM, DM, 0);
}